// round 16
// baseline (speedup 1.0000x reference)
#include <cuda_runtime.h>
#include <cuda_fp16.h>
#include <cstdint>
#include <cstddef>

#define BB 4
#define SS 512
#define EE 512
#define HIDD 2048
#define HH 8
#define DD 64
#define RFULL 201
#define RUSE 101
#define MR (BB*SS)   // 2048

// ---------------- fp32 scratch ----------------------------------------------
__device__ __align__(128) float g_q [MR*EE];
__device__ __align__(128) float g_ke[MR*EE];
__device__ __align__(128) float g_krt[RFULL*EE];
__device__ __align__(128) float g_t1[RFULL*HH];
__device__ __align__(128) float g_b0t[MR*HH];
__device__ __align__(128) float g_P[(size_t)MR*HH*RUSE];
__device__ __align__(128) float g_v [MR*EE];

// ---------------- fp16 scratch ----------------------------------------------
__device__ __align__(128) __half g_xnh[MR*EE];
__device__ __align__(128) __half g_xh [MR*HIDD];
__device__ __align__(128) __half g_vnh[MR*EE];
__device__ __align__(128) __half g_h1h[MR*HIDD];
__device__ __align__(128) __half g_reh[RFULL*EE + 64], g_rel_[RFULL*EE + 64];
__device__ __align__(128) __half g_qh [MR*EE], g_ql [MR*EE];
__device__ __align__(128) __half g_keh[MR*EE];
__device__ __align__(128) __half g_kvh[MR*EE];
__device__ __align__(128) __half g_krt16[HH*128*DD];   // zero-padded rows 101..127
// weights, transposed to [N][K], single fp16
__device__ __align__(128) __half g_wb0h[HIDD*EE];
__device__ __align__(128) __half g_wqkvh[3*EE*HIDD];
__device__ __align__(128) __half g_wkrh[EE*EE];
__device__ __align__(128) __half g_w11h[HIDD*EE];
__device__ __align__(128) __half g_w12h[EE*HIDD];

// ---------------- PTX helpers -----------------------------------------------
__device__ __forceinline__ uint32_t s2u(const void* p){
    uint32_t a;
    asm("{ .reg .u64 t; cvta.to.shared.u64 t, %1; cvt.u32.u64 %0, t; }" : "=r"(a) : "l"(p));
    return a;
}
__device__ __forceinline__ void cpa16(uint32_t dst, const void* src, uint32_t sz){
    asm volatile("cp.async.cg.shared.global [%0], [%1], 16, %2;" :: "r"(dst), "l"(src), "r"(sz));
}
__device__ __forceinline__ void cpcommit(){ asm volatile("cp.async.commit_group;" ::: "memory"); }
__device__ __forceinline__ void cpwait0(){ asm volatile("cp.async.wait_group 0;" ::: "memory"); }
__device__ __forceinline__ void cpwait1(){ asm volatile("cp.async.wait_group 1;" ::: "memory"); }

__device__ __forceinline__ void ldsm4(uint32_t* r, uint32_t addr){
    asm volatile("ldmatrix.sync.aligned.m8n8.x4.shared.b16 {%0,%1,%2,%3}, [%4];"
        : "=r"(r[0]), "=r"(r[1]), "=r"(r[2]), "=r"(r[3]) : "r"(addr));
}
__device__ __forceinline__ void ldsm4t(uint32_t* r, uint32_t addr){
    asm volatile("ldmatrix.sync.aligned.m8n8.x4.trans.shared.b16 {%0,%1,%2,%3}, [%4];"
        : "=r"(r[0]), "=r"(r[1]), "=r"(r[2]), "=r"(r[3]) : "r"(addr));
}
__device__ __forceinline__ void mma16816(float* d, const uint32_t* a, const uint32_t* b){
    asm volatile("mma.sync.aligned.m16n8k16.row.col.f32.f16.f16.f32 "
        "{%0,%1,%2,%3}, {%4,%5,%6,%7}, {%8,%9}, {%0,%1,%2,%3};"
        : "+f"(d[0]), "+f"(d[1]), "+f"(d[2]), "+f"(d[3])
        : "r"(a[0]), "r"(a[1]), "r"(a[2]), "r"(a[3]), "r"(b[0]), "r"(b[1]));
}
__device__ __forceinline__ uint32_t packh(__half a, __half b){
    return (uint32_t)__half_as_ushort(a) | ((uint32_t)__half_as_ushort(b) << 16);
}

// geometry: k-chunk 64, rows padded to 72 halves (144 B)
#define KC 64
#define KSTRIDE 72
#define ROWB 144
#define TILE_B (128*ROWB)                 // 18432
#define STAGE1P (2*TILE_B)                // (A, B) 128x128 1-pass
#define GSMEM1P (2*STAGE1P)               // 73728
#define STAGE2P (3*TILE_B)                // (Ah, Al, B)  kr only
#define GSMEM2P (2*STAGE2P)               // 110592

#define TILE_A2 (128*ROWB)
#define TILE_B2 (256*ROWB)
#define STAGEBIG (TILE_A2 + TILE_B2)      // 55296
#define GSMEMBIG (2*STAGEBIG)             // 110592

#define TILE_A64 (64*ROWB)                // 9216
#define STAGE64 (TILE_A64 + TILE_B)       // 27648
#define GSMEM64 (2*STAGE64)               // 55296

// flash attention: q tile 128x64, kv tiles 64x64
#define QTILE_B (128*ROWB)
#define ATILE_B (64*ROWB)
#define FA_SMEM (2*QTILE_B + 4*ATILE_B)   // 73728

// pgemm: qh tile + ql tile + krt16 tile
#define PK_SMEM (3*TILE_B)                // 55296

// ---------------- loaders ----------------------------------------------------
template<int TILES>
__device__ __forceinline__ void load_chunk128(uint32_t stage, int tid,
    const __half* __restrict__ A0, const __half* __restrict__ A1,
    const __half* __restrict__ Bh,
    int m0, int n0, int k0, int M, int K)
{
    #pragma unroll
    for (int t = 0; t < TILES; t++){
        const __half* gp = (t==0)?A0:(t==TILES-1)?Bh:A1;
        int row0 = (t < TILES-1) ? m0 : n0;
        uint32_t tb = stage + t*TILE_B;
        #pragma unroll
        for (int i = 0; i < 4; i++){
            int s = i*256 + tid;
            int r = s >> 3, seg = s & 7;
            int gr = row0 + r;
            uint32_t sz = 16u;
            if (t < TILES-1 && gr >= M){ sz = 0u; gr = M - 1; }
            cpa16(tb + (uint32_t)(r*ROWB + seg*16),
                  gp + (size_t)gr*K + k0 + seg*8, sz);
        }
    }
    cpcommit();
}

__device__ __forceinline__ void load_chunk_big(uint32_t stage, int tid,
    const __half* __restrict__ Ah, const __half* __restrict__ Bh,
    int m0, int n0, int k0, int K)
{
    #pragma unroll
    for (int i = 0; i < 4; i++){
        int s = i*256 + tid;
        int r = s >> 3, seg = s & 7;
        cpa16(stage + (uint32_t)(r*ROWB + seg*16),
              Ah + (size_t)(m0 + r)*K + k0 + seg*8, 16u);
    }
    uint32_t tb = stage + TILE_A2;
    #pragma unroll
    for (int i = 0; i < 8; i++){
        int s = i*256 + tid;
        int r = s >> 3, seg = s & 7;
        cpa16(tb + (uint32_t)(r*ROWB + seg*16),
              Bh + (size_t)(n0 + r)*K + k0 + seg*8, 16u);
    }
    cpcommit();
}

__device__ __forceinline__ void load_chunk64(uint32_t stage, int tid,
    const __half* __restrict__ A, const __half* __restrict__ B,
    int m0, int n0, int k0, int K)
{
    #pragma unroll
    for (int i = 0; i < 2; i++){
        int s = i*256 + tid;
        int r = s >> 3, seg = s & 7;
        cpa16(stage + (uint32_t)(r*ROWB + seg*16),
              A + (size_t)(m0 + r)*K + k0 + seg*8, 16u);
    }
    uint32_t tb = stage + TILE_A64;
    #pragma unroll
    for (int i = 0; i < 4; i++){
        int s = i*256 + tid;
        int r = s >> 3, seg = s & 7;
        cpa16(tb + (uint32_t)(r*ROWB + seg*16),
              B + (size_t)(n0 + r)*K + k0 + seg*8, 16u);
    }
    cpcommit();
}

// ---------------- 128x128 mainloop (PASSES = 1 or 2) -------------------------
template<int PASSES>
__device__ __forceinline__ void mainloop128(uint32_t sb, int tid, int lane, int warp,
    const __half* A0, const __half* A1, const __half* Bh,
    int m0, int n0, int M, int K, float acc[4][4][4])
{
    const int TILES = PASSES + 1;
    const int STG = TILES*TILE_B;
    int a_row  = (warp >> 2)*64 + (lane & 15);
    int a_col8 = (lane >> 4)*8;
    int b_row  = (warp & 3)*32 + (lane & 7) + ((lane & 16) ? 8 : 0);
    int b_col8 = ((lane & 8) ? 8 : 0);

    const int NC = K / KC;
    uint32_t st0 = sb, st1 = sb + STG;
    load_chunk128<TILES>(st0, tid, A0, A1, Bh, m0, n0, 0, M, K);

    for (int c = 0; c < NC; c++){
        uint32_t cur = (c & 1) ? st1 : st0;
        if (c + 1 < NC)
            load_chunk128<TILES>((c & 1) ? st0 : st1, tid, A0, A1, Bh, m0, n0, (c+1)*KC, M, K);
        if (c + 1 < NC) cpwait1(); else cpwait0();
        __syncthreads();

        uint32_t cA0 = cur, cA1 = cur + TILE_B, cB = cur + (TILES-1)*TILE_B;
        #pragma unroll
        for (int ks = 0; ks < 4; ks++){
            int k0 = ks*16;
            uint32_t a0[4][4], a1[4][4], bh[2][4];
            #pragma unroll
            for (int mt = 0; mt < 4; mt++){
                uint32_t off = (uint32_t)((a_row + mt*16)*KSTRIDE + k0 + a_col8)*2u;
                ldsm4(a0[mt], cA0 + off);
                if (PASSES == 2) ldsm4(a1[mt], cA1 + off);
            }
            #pragma unroll
            for (int p = 0; p < 2; p++){
                uint32_t off = (uint32_t)((b_row + p*16)*KSTRIDE + k0 + b_col8)*2u;
                ldsm4(bh[p], cB + off);
            }
            #pragma unroll
            for (int mt = 0; mt < 4; mt++)
                #pragma unroll
                for (int nt = 0; nt < 4; nt++)
                    mma16816(acc[mt][nt], a0[mt], &bh[nt >> 1][(nt & 1)*2]);
            if (PASSES == 2){
                #pragma unroll
                for (int mt = 0; mt < 4; mt++)
                    #pragma unroll
                    for (int nt = 0; nt < 4; nt++)
                        mma16816(acc[mt][nt], a1[mt], &bh[nt >> 1][(nt & 1)*2]);
            }
        }
        __syncthreads();
    }
}

// EPI: 0 fp32+bias, 2 fp32+bias+res ; PASSES 1 or 2
template<int EPI, int PASSES>
__global__ __launch_bounds__(256, 2)
void gemm128(const __half* A0, const __half* A1, const __half* Bh,
             const float* __restrict__ bias, const float* __restrict__ res,
             float* __restrict__ Cf, int M, int N, int K)
{
    extern __shared__ char smem[];
    uint32_t sb = s2u(smem);
    int tid = threadIdx.x, lane = tid & 31, warp = tid >> 5;
    int m0 = blockIdx.y*128, n0 = blockIdx.x*128;
    float acc[4][4][4];
    #pragma unroll
    for (int a = 0; a < 4; a++)
        #pragma unroll
        for (int b = 0; b < 4; b++)
            #pragma unroll
            for (int c = 0; c < 4; c++) acc[a][b][c] = 0.f;

    mainloop128<PASSES>(sb, tid, lane, warp, A0, A1, Bh, m0, n0, M, K, acc);

    int gg = lane >> 2, tig = lane & 3;
    int wm = warp >> 2, wn = warp & 3;
    #pragma unroll
    for (int mt = 0; mt < 4; mt++)
        #pragma unroll
        for (int half = 0; half < 2; half++){
            int row = m0 + wm*64 + mt*16 + gg + half*8;
            if (row >= M) continue;
            #pragma unroll
            for (int nt = 0; nt < 4; nt++){
                int col = n0 + wn*32 + nt*8 + tig*2;
                float v0 = acc[mt][nt][half*2 + 0] + bias[col];
                float v1 = acc[mt][nt][half*2 + 1] + bias[col + 1];
                size_t o = (size_t)row*N + col;
                if (EPI == 2){
                    float2 rv = *(const float2*)&res[o];
                    v0 += rv.x; v1 += rv.y;
                }
                *(float2*)&Cf[o] = make_float2(v0, v1);
            }
        }
}

// merged qkv on 128x128 tiles (R15 win): N=1536, z = blockIdx.x>>2
__global__ __launch_bounds__(256, 2)
void gemm_qkv128(const __half* Ah, const __half* Bh,
                 const float* b0, const float* b1, const float* b2,
                 float* f0, float* f1,
                 __half* c0h, __half* c0l, __half* c1h, __half* c2h,
                 int M, int K)
{
    extern __shared__ char smem[];
    uint32_t sb = s2u(smem);
    int tid = threadIdx.x, lane = tid & 31, warp = tid >> 5;
    int m0 = blockIdx.y*128, n0 = blockIdx.x*128;
    float acc[4][4][4];
    #pragma unroll
    for (int a = 0; a < 4; a++)
        #pragma unroll
        for (int b = 0; b < 4; b++)
            #pragma unroll
            for (int c = 0; c < 4; c++) acc[a][b][c] = 0.f;

    mainloop128<1>(sb, tid, lane, warp, Ah, nullptr, Bh, m0, n0, M, K, acc);

    int z = blockIdx.x >> 2;
    const float* bias = (z==0)?b0:(z==1)?b1:b2;
    float* Cf = (z==0)?f0:(z==1)?f1:nullptr;
    __half* Ch = (z==0)?c0h:(z==1)?c1h:c2h;
    __half* Cl = (z==0)?c0l:nullptr;
    int n0l = (blockIdx.x & 3)*128;

    int gg = lane >> 2, tig = lane & 3;
    int wm = warp >> 2, wn = warp & 3;
    #pragma unroll
    for (int mt = 0; mt < 4; mt++)
        #pragma unroll
        for (int half = 0; half < 2; half++){
            int row = m0 + wm*64 + mt*16 + gg + half*8;
            #pragma unroll
            for (int nt = 0; nt < 4; nt++){
                int col = n0l + wn*32 + nt*8 + tig*2;
                float v0 = acc[mt][nt][half*2 + 0] + bias[col];
                float v1 = acc[mt][nt][half*2 + 1] + bias[col + 1];
                size_t o = (size_t)row*512 + col;
                if (Cf) *(float2*)&Cf[o] = make_float2(v0, v1);
                __half h0 = __float2half_rn(v0);
                __half h1 = __float2half_rn(v1);
                *(uint32_t*)((char*)Ch + o*2) = packh(h0, h1);
                if (Cl){
                    __half l0 = __float2half_rn(v0 - __half2float(h0));
                    __half l1 = __float2half_rn(v1 - __half2float(h1));
                    *(uint32_t*)((char*)Cl + o*2) = packh(l0, l1);
                }
            }
        }
}

// ---------------- 128x256 mainloop (single pass) — wb0 / FFN1 ----------------
__device__ __forceinline__ void mainloop_big(uint32_t sb, int tid, int lane, int warp,
    const __half* Ah, const __half* Bh,
    int m0, int n0, int K, float acc[4][8][4])
{
    int a_row  = (warp >> 2)*64 + (lane & 15);
    int a_col8 = (lane >> 4)*8;
    int b_rowb = (warp & 3)*64 + (lane & 7) + ((lane & 16) ? 8 : 0);
    int b_col8 = ((lane & 8) ? 8 : 0);

    const int NC = K / KC;
    uint32_t st0 = sb, st1 = sb + STAGEBIG;
    load_chunk_big(st0, tid, Ah, Bh, m0, n0, 0, K);

    for (int c = 0; c < NC; c++){
        uint32_t cur = (c & 1) ? st1 : st0;
        if (c + 1 < NC)
            load_chunk_big((c & 1) ? st0 : st1, tid, Ah, Bh, m0, n0, (c+1)*KC, K);
        if (c + 1 < NC) cpwait1(); else cpwait0();
        __syncthreads();

        uint32_t cA = cur, cB = cur + TILE_A2;
        #pragma unroll
        for (int ks = 0; ks < 4; ks++){
            int k0 = ks*16;
            uint32_t ah[4][4];
            #pragma unroll
            for (int mt = 0; mt < 4; mt++){
                uint32_t off = (uint32_t)((a_row + mt*16)*KSTRIDE + k0 + a_col8)*2u;
                ldsm4(ah[mt], cA + off);
            }
            #pragma unroll
            for (int h2 = 0; h2 < 2; h2++){
                uint32_t bh[2][4];
                #pragma unroll
                for (int p = 0; p < 2; p++){
                    uint32_t off = (uint32_t)((b_rowb + (h2*2 + p)*16)*KSTRIDE + k0 + b_col8)*2u;
                    ldsm4(bh[p], cB + off);
                }
                #pragma unroll
                for (int mt = 0; mt < 4; mt++)
                    #pragma unroll
                    for (int j = 0; j < 4; j++)
                        mma16816(acc[mt][h2*4 + j], ah[mt], &bh[j >> 1][(j & 1)*2]);
            }
        }
        __syncthreads();
    }
}

__global__ __launch_bounds__(256, 1)
void gemm_big_relu(const __half* Ah, const __half* Bh,
                   const float* __restrict__ bias,
                   __half* __restrict__ Ch, int M, int N, int K)
{
    extern __shared__ char smem[];
    uint32_t sb = s2u(smem);
    int tid = threadIdx.x, lane = tid & 31, warp = tid >> 5;
    int m0 = blockIdx.y*128, n0 = blockIdx.x*256;
    float acc[4][8][4];
    #pragma unroll
    for (int a = 0; a < 4; a++)
        #pragma unroll
        for (int b = 0; b < 8; b++)
            #pragma unroll
            for (int c = 0; c < 4; c++) acc[a][b][c] = 0.f;

    mainloop_big(sb, tid, lane, warp, Ah, Bh, m0, n0, K, acc);

    int gg = lane >> 2, tig = lane & 3;
    int wm = warp >> 2, wn = warp & 3;
    #pragma unroll
    for (int mt = 0; mt < 4; mt++)
        #pragma unroll
        for (int half = 0; half < 2; half++){
            int row = m0 + wm*64 + mt*16 + gg + half*8;
            #pragma unroll
            for (int nt8 = 0; nt8 < 8; nt8++){
                int col = n0 + wn*64 + nt8*8 + tig*2;
                float v0 = fmaxf(acc[mt][nt8][half*2 + 0] + bias[col],     0.f);
                float v1 = fmaxf(acc[mt][nt8][half*2 + 1] + bias[col + 1], 0.f);
                size_t o = (size_t)row*N + col;
                *(uint32_t*)((char*)Ch + o*2) = packh(__float2half_rn(v0), __float2half_rn(v1));
            }
        }
}

// ---------------- 64x128 GEMM (FFN2) -----------------------------------------
__global__ __launch_bounds__(256, 2)
void gemm64_res(const __half* __restrict__ A, const __half* __restrict__ B,
                const float* __restrict__ bias, const float* __restrict__ res,
                float* __restrict__ Cf, int M, int N, int K)
{
    extern __shared__ char smem[];
    uint32_t sb = s2u(smem);
    int tid = threadIdx.x, lane = tid & 31, warp = tid >> 5;
    int m0 = blockIdx.y*64, n0 = blockIdx.x*128;

    int a_row  = (warp >> 2)*32 + (lane & 15);
    int a_col8 = (lane >> 4)*8;
    int b_row  = (warp & 3)*32 + (lane & 7) + ((lane & 16) ? 8 : 0);
    int b_col8 = ((lane & 8) ? 8 : 0);

    float acc[2][4][4];
    #pragma unroll
    for (int a = 0; a < 2; a++)
        #pragma unroll
        for (int b = 0; b < 4; b++)
            #pragma unroll
            for (int c = 0; c < 4; c++) acc[a][b][c] = 0.f;

    const int NC = K / KC;
    uint32_t st0 = sb, st1 = sb + STAGE64;
    load_chunk64(st0, tid, A, B, m0, n0, 0, K);

    for (int c = 0; c < NC; c++){
        uint32_t cur = (c & 1) ? st1 : st0;
        if (c + 1 < NC)
            load_chunk64((c & 1) ? st0 : st1, tid, A, B, m0, n0, (c+1)*KC, K);
        if (c + 1 < NC) cpwait1(); else cpwait0();
        __syncthreads();

        uint32_t cA = cur, cB = cur + TILE_A64;
        #pragma unroll
        for (int ks = 0; ks < 4; ks++){
            int k0 = ks*16;
            uint32_t af[2][4], bh[2][4];
            #pragma unroll
            for (int mt = 0; mt < 2; mt++){
                uint32_t off = (uint32_t)((a_row + mt*16)*KSTRIDE + k0 + a_col8)*2u;
                ldsm4(af[mt], cA + off);
            }
            #pragma unroll
            for (int p = 0; p < 2; p++){
                uint32_t off = (uint32_t)((b_row + p*16)*KSTRIDE + k0 + b_col8)*2u;
                ldsm4(bh[p], cB + off);
            }
            #pragma unroll
            for (int mt = 0; mt < 2; mt++)
                #pragma unroll
                for (int nt = 0; nt < 4; nt++)
                    mma16816(acc[mt][nt], af[mt], &bh[nt >> 1][(nt & 1)*2]);
        }
        __syncthreads();
    }

    int gg = lane >> 2, tig = lane & 3;
    int wm = warp >> 2, wn = warp & 3;
    #pragma unroll
    for (int mt = 0; mt < 2; mt++)
        #pragma unroll
        for (int half = 0; half < 2; half++){
            int row = m0 + wm*32 + mt*16 + gg + half*8;
            #pragma unroll
            for (int nt = 0; nt < 4; nt++){
                int col = n0 + wn*32 + nt*8 + tig*2;
                float v0 = acc[mt][nt][half*2 + 0] + bias[col];
                float v1 = acc[mt][nt][half*2 + 1] + bias[col + 1];
                size_t o = (size_t)row*N + col;
                float2 rv = *(const float2*)&res[o];
                *(float2*)&Cf[o] = make_float2(v0 + rv.x, v1 + rv.y);
            }
        }
}

// ---------------- krt fp32 -> fp16 (zero-padded to 128 rows) -----------------
__global__ void convK(const float* __restrict__ krt, __half* __restrict__ K16)
{
    int idx = blockIdx.x*256 + threadIdx.x;      // over 8*128*64 = 65536
    int h = idx >> 13;
    int rk = idx & 8191;
    int row = rk >> 6, k = rk & 63;
    float v = (row < RUSE) ? krt[(size_t)row*EE + h*DD + k] : 0.f;
    K16[idx] = __float2half_rn(v);
}

// ---------------- tensor-core P table: P[m,h,r] = q_h(m).krt_h(r) + t1[r,h] --
// grid (16 m-tiles, 8 h), block 256 (8 warps x 16 rows)
__global__ __launch_bounds__(256, 1)
void pgemm(const __half* __restrict__ qh, const __half* __restrict__ ql,
           const __half* __restrict__ K16,
           const float* __restrict__ t1, float* __restrict__ P)
{
    extern __shared__ char smem[];
    uint32_t sb = s2u(smem);
    int tid = threadIdx.x, lane = tid & 31, warp = tid >> 5;
    int m0 = blockIdx.x*128, h = blockIdx.y;

    uint32_t sAh = sb, sAl = sb + TILE_B, sB = sb + 2*TILE_B;
    // load q hi/lo rows m0..m0+127, cols h*64..h*64+63
    #pragma unroll
    for (int t = 0; t < 2; t++){
        const __half* gp = t ? ql : qh;
        uint32_t tb = t ? sAl : sAh;
        #pragma unroll
        for (int i = 0; i < 4; i++){
            int s = i*256 + tid;
            int r = s >> 3, seg = s & 7;
            cpa16(tb + (uint32_t)(r*ROWB + seg*16),
                  gp + (size_t)(m0 + r)*EE + h*DD + seg*8, 16u);
        }
    }
    // load krt16[h]: 128 rows x 64 halves
    #pragma unroll
    for (int i = 0; i < 4; i++){
        int s = i*256 + tid;
        int r = s >> 3, seg = s & 7;
        cpa16(sB + (uint32_t)(r*ROWB + seg*16),
              K16 + (size_t)h*128*DD + r*DD + seg*8, 16u);
    }
    cpcommit(); cpwait0();
    __syncthreads();

    int a_row  = warp*16 + (lane & 15);
    int a_col8 = (lane >> 4)*8;
    int b_row  = (lane & 7) + ((lane & 16) ? 8 : 0);
    int b_col8 = ((lane & 8) ? 8 : 0);

    float acc[16][4];
    #pragma unroll
    for (int nt = 0; nt < 16; nt++)
        #pragma unroll
        for (int c = 0; c < 4; c++) acc[nt][c] = 0.f;

    #pragma unroll
    for (int ks = 0; ks < 4; ks++){
        int k0 = ks*16;
        uint32_t aq[4], aql[4], bf[8][4];
        uint32_t offA = (uint32_t)(a_row*KSTRIDE + k0 + a_col8)*2u;
        ldsm4(aq,  sAh + offA);
        ldsm4(aql, sAl + offA);
        #pragma unroll
        for (int p = 0; p < 8; p++){
            uint32_t off = (uint32_t)((p*16 + b_row)*KSTRIDE + k0 + b_col8)*2u;
            ldsm4(bf[p], sB + off);
        }
        #pragma unroll
        for (int nt = 0; nt < 16; nt++)
            mma16816(acc[nt], aq, &bf[nt >> 1][(nt & 1)*2]);
        #pragma unroll
        for (int nt = 0; nt < 16; nt++)
            mma16816(acc[nt], aql, &bf[nt >> 1][(nt & 1)*2]);
    }

    int gg = lane >> 2, tig = lane & 3;
    #pragma unroll
    for (int half = 0; half < 2; half++){
        int m = m0 + warp*16 + gg + half*8;
        float* Pp = P + ((size_t)m*HH + h)*RUSE;
        #pragma unroll
        for (int nt = 0; nt < 16; nt++){
            #pragma unroll
            for (int e = 0; e < 2; e++){
                int r = nt*8 + tig*2 + e;
                if (r < RUSE)
                    Pp[r] = acc[nt][half*2 + e] + t1[r*HH + h];
            }
        }
    }
}

// ---------------- fused flash attention: 128-row q tiles ---------------------
__global__ __launch_bounds__(256) void flash_att(
    const __half* __restrict__ qh, const __half* __restrict__ ql,
    const __half* __restrict__ keh, const __half* __restrict__ kvh,
    const float* __restrict__ P, const float* __restrict__ b0t,
    const float* __restrict__ vals, float* __restrict__ V)
{
    extern __shared__ char smem[];
    uint32_t sb = s2u(smem);
    int tid = threadIdx.x, lane = tid & 31, warp = tid >> 5;
    int it = blockIdx.x, bh = blockIdx.y, b = bh >> 3, h = bh & 7;
    int i0 = it*128;
    int NCH = 2*it + 2;

    uint32_t sQH = sb, sQL = sb + QTILE_B;
    uint32_t st0 = sb + 2*QTILE_B;
    uint32_t st1 = st0 + 2*ATILE_B;

    #pragma unroll
    for (int t = 0; t < 2; t++){
        const __half* gp = t ? ql : qh;
        uint32_t tb = t ? sQL : sQH;
        #pragma unroll
        for (int i = 0; i < 4; i++){
            int s = i*256 + tid;
            int r = s >> 3, seg = s & 7;
            cpa16(tb + (uint32_t)(r*ROWB + seg*16),
                  gp + ((size_t)(b*SS + i0 + r))*EE + h*DD + seg*8, 16u);
        }
    }
    #pragma unroll
    for (int t = 0; t < 2; t++){
        const __half* gp = t ? kvh : keh;
        uint32_t tb = st0 + t*ATILE_B;
        #pragma unroll
        for (int i = 0; i < 2; i++){
            int s = i*256 + tid;
            int r = s >> 3, seg = s & 7;
            cpa16(tb + (uint32_t)(r*ROWB + seg*16),
                  gp + ((size_t)(b*SS + r))*EE + h*DD + seg*8, 16u);
        }
    }
    cpcommit();

    int gg = lane >> 2, tig = lane & 3;
    int a_row  = warp*16 + (lane & 15);
    int a_col8 = (lane >> 4)*8;
    int b_rowb = (lane & 7) + ((lane & 16) ? 8 : 0);
    int b_col8 = ((lane & 8) ? 8 : 0);
    int bt_row = lane & 15;
    int bt_colb = ((lane & 16) ? 8 : 0);

    int gi0 = i0 + warp*16 + gg;
    int gi1 = gi0 + 8;
    const float* Pr0 = P + ((size_t)(b*SS + gi0)*HH + h)*RUSE + 100;
    const float* Pr1 = P + ((size_t)(b*SS + gi1)*HH + h)*RUSE + 100;

    float m_st[2] = {-1e30f, -1e30f};
    float l_st[2] = {0.f, 0.f};
    float acc_o[8][4];
    #pragma unroll
    for (int nt = 0; nt < 8; nt++)
        #pragma unroll
        for (int c = 0; c < 4; c++) acc_o[nt][c] = 0.f;

    for (int c = 0; c < NCH; c++){
        uint32_t cur = (c & 1) ? st1 : st0;
        if (c + 1 < NCH){
            uint32_t nxt = (c & 1) ? st0 : st1;
            int j0n = (c + 1)*64;
            #pragma unroll
            for (int t = 0; t < 2; t++){
                const __half* gp = t ? kvh : keh;
                uint32_t tb = nxt + t*ATILE_B;
                #pragma unroll
                for (int i = 0; i < 2; i++){
                    int s = i*256 + tid;
                    int r = s >> 3, seg = s & 7;
                    cpa16(tb + (uint32_t)(r*ROWB + seg*16),
                          gp + ((size_t)(b*SS + j0n + r))*EE + h*DD + seg*8, 16u);
                }
            }
            cpcommit();
        }
        if (c + 1 < NCH) cpwait1(); else cpwait0();
        __syncthreads();

        int j0 = c*64;
        uint32_t cK = cur, cV = cur + ATILE_B;

        float s_acc[8][4];
        #pragma unroll
        for (int nt = 0; nt < 8; nt++)
            #pragma unroll
            for (int e = 0; e < 4; e++) s_acc[nt][e] = 0.f;
        #pragma unroll
        for (int ks = 0; ks < 4; ks++){
            int k0 = ks*16;
            uint32_t aq[4], aql[4], bf[4][4];
            uint32_t offA = (uint32_t)(a_row*KSTRIDE + k0 + a_col8)*2u;
            ldsm4(aq,  sQH + offA);
            ldsm4(aql, sQL + offA);
            #pragma unroll
            for (int p = 0; p < 4; p++){
                uint32_t off = (uint32_t)((p*16 + b_rowb)*KSTRIDE + k0 + b_col8)*2u;
                ldsm4(bf[p], cK + off);
            }
            #pragma unroll
            for (int nt = 0; nt < 8; nt++)
                mma16816(s_acc[nt], aq, &bf[nt >> 1][(nt & 1)*2]);
            #pragma unroll
            for (int nt = 0; nt < 8; nt++)
                mma16816(s_acc[nt], aql, &bf[nt >> 1][(nt & 1)*2]);
        }

        float rowmax[2] = {-1e30f, -1e30f};
        #pragma unroll
        for (int nt = 0; nt < 8; nt++){
            #pragma unroll
            for (int e = 0; e < 2; e++){
                int j = j0 + nt*8 + tig*2 + e;
                float bv = b0t[(size_t)(b*SS + j)*HH + h];
                #pragma unroll
                for (int hh = 0; hh < 2; hh++){
                    int gi = hh ? gi1 : gi0;
                    int ci = hh*2 + e;
                    float val;
                    if (j > gi){
                        val = -1e30f;
                    } else {
                        int off = j - gi;
                        if (off < -100) off = -100;
                        val = s_acc[nt][ci]*0.125f + (hh ? Pr1 : Pr0)[off] + bv;
                    }
                    s_acc[nt][ci] = val;
                    rowmax[hh] = fmaxf(rowmax[hh], val);
                }
            }
        }
        #pragma unroll
        for (int hh = 0; hh < 2; hh++){
            rowmax[hh] = fmaxf(rowmax[hh], __shfl_xor_sync(0xffffffffu, rowmax[hh], 1));
            rowmax[hh] = fmaxf(rowmax[hh], __shfl_xor_sync(0xffffffffu, rowmax[hh], 2));
        }
        float mnew[2], scale[2], rsum[2] = {0.f, 0.f};
        #pragma unroll
        for (int hh = 0; hh < 2; hh++){
            mnew[hh]  = fmaxf(m_st[hh], rowmax[hh]);
            scale[hh] = __expf(m_st[hh] - mnew[hh]);
            m_st[hh]  = mnew[hh];
        }
        #pragma unroll
        for (int nt = 0; nt < 8; nt++)
            #pragma unroll
            for (int ci = 0; ci < 4; ci++){
                int hh = ci >> 1;
                float p = __expf(s_acc[nt][ci] - mnew[hh]);
                s_acc[nt][ci] = p;
                rsum[hh] += p;
            }
        #pragma unroll
        for (int hh = 0; hh < 2; hh++){
            rsum[hh] += __shfl_xor_sync(0xffffffffu, rsum[hh], 1);
            rsum[hh] += __shfl_xor_sync(0xffffffffu, rsum[hh], 2);
            l_st[hh] = l_st[hh]*scale[hh] + rsum[hh];
        }
        #pragma unroll
        for (int nt = 0; nt < 8; nt++)
            #pragma unroll
            for (int ci = 0; ci < 4; ci++)
                acc_o[nt][ci] *= scale[ci >> 1];

        uint32_t pa[4][4], pl[4][4];
        #pragma unroll
        for (int ks2 = 0; ks2 < 4; ks2++){
            #pragma unroll
            for (int half8 = 0; half8 < 2; half8++){
                int nt = ks2*2 + half8;
                __half h0 = __float2half_rn(s_acc[nt][0]);
                __half h1 = __float2half_rn(s_acc[nt][1]);
                __half h2 = __float2half_rn(s_acc[nt][2]);
                __half h3 = __float2half_rn(s_acc[nt][3]);
                pa[ks2][0 + half8*2] = packh(h0, h1);
                pa[ks2][1 + half8*2] = packh(h2, h3);
                __half l0 = __float2half_rn(s_acc[nt][0] - __half2float(h0));
                __half l1 = __float2half_rn(s_acc[nt][1] - __half2float(h1));
                __half l2 = __float2half_rn(s_acc[nt][2] - __half2float(h2));
                __half l3 = __float2half_rn(s_acc[nt][3] - __half2float(h3));
                pl[ks2][0 + half8*2] = packh(l0, l1);
                pl[ks2][1 + half8*2] = packh(l2, l3);
            }
        }

        #pragma unroll
        for (int ks2 = 0; ks2 < 4; ks2++){
            int k0 = ks2*16;
            uint32_t bv[4][4];
            #pragma unroll
            for (int grp = 0; grp < 4; grp++){
                uint32_t off = (uint32_t)((k0 + bt_row)*KSTRIDE + grp*16 + bt_colb)*2u;
                ldsm4t(bv[grp], cV + off);
            }
            #pragma unroll
            for (int nt = 0; nt < 8; nt++)
                mma16816(acc_o[nt], pa[ks2], &bv[nt >> 1][(nt & 1)*2]);
            #pragma unroll
            for (int nt = 0; nt < 8; nt++)
                mma16816(acc_o[nt], pl[ks2], &bv[nt >> 1][(nt & 1)*2]);
        }
        __syncthreads();
    }

    float inv[2] = {1.f / l_st[0], 1.f / l_st[1]};
    #pragma unroll
    for (int hh = 0; hh < 2; hh++){
        int gi = hh ? gi1 : gi0;
        #pragma unroll
        for (int nt = 0; nt < 8; nt++){
            int d = nt*8 + tig*2;
            size_t o = ((size_t)(b*SS + gi))*EE + h*DD + d;
            float2 rv = *(const float2*)&vals[o];
            *(float2*)&V[o] = make_float2(acc_o[nt][hh*2 + 0]*inv[hh] + rv.x,
                                          acc_o[nt][hh*2 + 1]*inv[hh] + rv.y);
        }
    }
}

// ---------------- fused weight conversion ------------------------------------
struct WTab {
    const float* W[7];
    __half* Th[7];
    int K[7];
    int N[7];
    int off[8];
};

__global__ void convWT_all(WTab tab)
{
    __shared__ float t[32][33];
    int bid = blockIdx.x;
    int e = 0;
    #pragma unroll
    for (int i = 1; i < 7; i++) if (bid >= tab.off[i]) e = i;
    int local = bid - tab.off[e];
    const float* W = tab.W[e];
    __half* Th = tab.Th[e];
    int K = tab.K[e], N = tab.N[e];
    int ntiles = N >> 5;
    int kt = local / ntiles, ct = local - kt*ntiles;
    int by = kt*32, bx = ct*32;
    int lx = threadIdx.x & 31, ly = threadIdx.x >> 5;
    #pragma unroll
    for (int i = 0; i < 32; i += 8)
        t[ly + i][lx] = W[(size_t)(by + ly + i)*N + bx + lx];
    __syncthreads();
    #pragma unroll
    for (int i = 0; i < 32; i += 8){
        int n = bx + ly + i, k = by + lx;
        Th[(size_t)n*K + k] = __float2half_rn(t[lx][ly + i]);
    }
}

__global__ void convA(const float* __restrict__ X, __half* __restrict__ H,
                      __half* __restrict__ L, int n)
{
    int i = blockIdx.x*256 + threadIdx.x;
    if (i < n){
        float x = X[i];
        __half h = __float2half_rn(x);
        H[i] = h;
        L[i] = __float2half_rn(x - __half2float(h));
    }
}

// ---------------- LayerNorm -> fp16 hi only ---------------------------------
__global__ void ln_h(const float* __restrict__ X, const float* __restrict__ g,
                     const float* __restrict__ bt, __half* __restrict__ Yh)
{
    int row = blockIdx.x;
    int tid = threadIdx.x;
    const float* x = X + (size_t)row*EE;
    float a = x[tid], c = x[tid + 256];
    float s  = a + c;
    float s2 = a*a + c*c;
    #pragma unroll
    for (int o = 16; o > 0; o >>= 1){
        s  += __shfl_xor_sync(0xffffffffu, s,  o);
        s2 += __shfl_xor_sync(0xffffffffu, s2, o);
    }
    __shared__ float sa[8], sbm[8];
    if ((tid & 31) == 0){ sa[tid>>5] = s; sbm[tid>>5] = s2; }
    __syncthreads();
    float ts = 0.f, ts2 = 0.f;
    #pragma unroll
    for (int w = 0; w < 8; w++){ ts += sa[w]; ts2 += sbm[w]; }
    float mean = ts * (1.f/512.f);
    float var  = ts2 * (1.f/512.f) - mean*mean;
    float r = rsqrtf(var + 1e-3f);
    Yh[(size_t)row*EE + tid]       = __float2half_rn((a - mean)*r*g[tid]       + bt[tid]);
    Yh[(size_t)row*EE + tid + 256] = __float2half_rn((c - mean)*r*g[tid + 256] + bt[tid + 256]);
}

// ---------------- fused dual N=8 projection ----------------------------------
__global__ void proj8_dual(
    const float* __restrict__ X0, const float* __restrict__ W0,
    const float* __restrict__ bp0, float* __restrict__ Y0, int n0,
    const float* __restrict__ X1, const float* __restrict__ W1,
    const float* __restrict__ bp1, float* __restrict__ Y1)
{
    int row = blockIdx.x;
    const float *X, *Wp, *bp;
    float* Y;
    int r;
    if (row < n0){ X = X0; Wp = W0; bp = bp0; Y = Y0; r = row; }
    else         { X = X1; Wp = W1; bp = bp1; Y = Y1; r = row - n0; }
    int tid = threadIdx.x;
    int h = tid & 7, seg = tid >> 3;
    const float* x = X + (size_t)r*EE;
    float s = 0.f;
    #pragma unroll
    for (int k = 0; k < 16; k++){
        int kk = seg*16 + k;
        s += x[kk] * Wp[kk*HH + h];
    }
    __shared__ float sm[256];
    sm[tid] = s;
    __syncthreads();
    if (tid < 8){
        float acc = bp[tid];
        #pragma unroll
        for (int sg = 0; sg < 32; sg++) acc += sm[sg*8 + tid];
        Y[(size_t)r*HH + tid] = acc;
    }
}

// ---------------- launch ----------------------------------------------------
extern "C" void kernel_launch(void* const* d_in, const int* in_sizes, int n_in,
                              void* d_out, int out_size)
{
    const float* values  = (const float*)d_in[0];
    const float* rel_enc = (const float*)d_in[2];
    const float* ln0_g   = (const float*)d_in[3];
    const float* ln0_b   = (const float*)d_in[4];
    const float* w_b0    = (const float*)d_in[5];
    const float* b_b0    = (const float*)d_in[6];
    const float* wq      = (const float*)d_in[7];
    const float* bq      = (const float*)d_in[8];
    const float* wke     = (const float*)d_in[9];
    const float* bke     = (const float*)d_in[10];
    const float* wkv     = (const float*)d_in[11];
    const float* bkv     = (const float*)d_in[12];
    const float* wkr     = (const float*)d_in[13];
    const float* bkr     = (const float*)d_in[14];
    const float* wab0    = (const float*)d_in[15];
    const float* bab0    = (const float*)d_in[16];
    const float* wab1    = (const float*)d_in[17];
    const float* bab1    = (const float*)d_in[18];
    const float* ln1_g   = (const float*)d_in[19];
    const float* ln1_b   = (const float*)d_in[20];
    const float* w11     = (const float*)d_in[21];
    const float* b11     = (const float*)d_in[22];
    const float* w12     = (const float*)d_in[23];
    const float* b12     = (const float*)d_in[24];
    float* out = (float*)d_out;

    float *p_q,*p_ke,*p_krt,*p_t1,*p_b0t,*p_P,*p_v;
    cudaGetSymbolAddress((void**)&p_q,   g_q);
    cudaGetSymbolAddress((void**)&p_ke,  g_ke);
    cudaGetSymbolAddress((void**)&p_krt, g_krt);
    cudaGetSymbolAddress((void**)&p_t1,  g_t1);
    cudaGetSymbolAddress((void**)&p_b0t, g_b0t);
    cudaGetSymbolAddress((void**)&p_P,   g_P);
    cudaGetSymbolAddress((void**)&p_v,   g_v);

    __half *xnh,*xh,*vnh,*h1h,*reh,*rel,*krt16;
    __half *qh,*ql,*keh,*kvh;
    __half *wb0h,*wqkvh,*wkrh,*w11h,*w12h;
    cudaGetSymbolAddress((void**)&xnh, g_xnh);
    cudaGetSymbolAddress((void**)&xh,  g_xh);
    cudaGetSymbolAddress((void**)&vnh, g_vnh);
    cudaGetSymbolAddress((void**)&h1h, g_h1h);
    cudaGetSymbolAddress((void**)&reh, g_reh); cudaGetSymbolAddress((void**)&rel, g_rel_);
    cudaGetSymbolAddress((void**)&krt16, g_krt16);
    cudaGetSymbolAddress((void**)&qh,  g_qh);  cudaGetSymbolAddress((void**)&ql,  g_ql);
    cudaGetSymbolAddress((void**)&keh, g_keh);
    cudaGetSymbolAddress((void**)&kvh, g_kvh);
    cudaGetSymbolAddress((void**)&wb0h, g_wb0h);
    cudaGetSymbolAddress((void**)&wqkvh, g_wqkvh);
    cudaGetSymbolAddress((void**)&wkrh, g_wkrh);
    cudaGetSymbolAddress((void**)&w11h, g_w11h);
    cudaGetSymbolAddress((void**)&w12h, g_w12h);

    cudaFuncSetAttribute((const void*)gemm128<0,2>, cudaFuncAttributeMaxDynamicSharedMemorySize, GSMEM2P);
    cudaFuncSetAttribute(gemm_qkv128,   cudaFuncAttributeMaxDynamicSharedMemorySize, GSMEM1P);
    cudaFuncSetAttribute(gemm_big_relu, cudaFuncAttributeMaxDynamicSharedMemorySize, GSMEMBIG);
    cudaFuncSetAttribute(gemm64_res,    cudaFuncAttributeMaxDynamicSharedMemorySize, GSMEM64);
    cudaFuncSetAttribute(pgemm,         cudaFuncAttributeMaxDynamicSharedMemorySize, PK_SMEM);
    cudaFuncSetAttribute(flash_att,     cudaFuncAttributeMaxDynamicSharedMemorySize, FA_SMEM);

    WTab tab;
    tab.W[0]=w_b0; tab.Th[0]=wb0h;              tab.K[0]=EE;   tab.N[0]=HIDD;
    tab.W[1]=wq;   tab.Th[1]=wqkvh;             tab.K[1]=HIDD; tab.N[1]=EE;
    tab.W[2]=wke;  tab.Th[2]=wqkvh + 512*HIDD;  tab.K[2]=HIDD; tab.N[2]=EE;
    tab.W[3]=wkv;  tab.Th[3]=wqkvh + 1024*HIDD; tab.K[3]=HIDD; tab.N[3]=EE;
    tab.W[4]=wkr;  tab.Th[4]=wkrh;              tab.K[4]=EE;   tab.N[4]=EE;
    tab.W[5]=w11;  tab.Th[5]=w11h;              tab.K[5]=EE;   tab.N[5]=HIDD;
    tab.W[6]=w12;  tab.Th[6]=w12h;              tab.K[6]=HIDD; tab.N[6]=EE;
    int total = 0;
    for (int i = 0; i < 7; i++){
        tab.off[i] = total;
        total += (tab.K[i]/32) * (tab.N[i]/32);
    }
    tab.off[7] = total;
    convWT_all<<<total, 256>>>(tab);
    convA<<<(RFULL*EE + 255)/256, 256>>>(rel_enc, reh, rel, RFULL*EE);

    // 1) LN0 -> fp16
    ln_h<<<MR, 256>>>(values, ln0_g, ln0_b, xnh);
    // 2) x = relu(xn @ w_b0 + b_b0)  [128x256, 128 blocks]
    gemm_big_relu<<<dim3(HIDD/256, MR/128), 256, GSMEMBIG>>>(
        xnh, wb0h, b_b0, xh, MR, HIDD, EE);
    // 3) merged q/ke/kv              [128x128, 192 blocks, occ 2]
    gemm_qkv128<<<dim3(12, MR/128), 256, GSMEM1P>>>(
        xh, wqkvh, bq, bke, bkv, p_q, p_ke, qh, ql, keh, kvh, MR, HIDD);
    // 4) kr_table (2-pass)
    gemm128<0,2><<<dim3(EE/128, 2), 256, GSMEM2P>>>(
        reh, rel, wkrh, bkr, nullptr, p_krt, RFULL, EE, EE);
    // 5) bias0 + t1 (fused) ; krt -> fp16 padded
    proj8_dual<<<MR + RFULL, 256>>>(p_ke, wab0, bab0, p_b0t, MR,
                                    p_krt, wab1, bab1, p_t1);
    convK<<<(HH*128*DD)/256, 256>>>(p_krt, krt16);
    // 6) P via tensor cores          [128 blocks]
    pgemm<<<dim3(MR/128, HH), 256, PK_SMEM>>>(qh, ql, krt16, p_t1, p_P);
    // 7) fused flash attention -> v
    flash_att<<<dim3(4, BB*HH), 256, FA_SMEM>>>(
        qh, ql, keh, kvh, p_P, p_b0t, values, p_v);
    // 8) LN1 -> fp16
    ln_h<<<MR, 256>>>(p_v, ln1_g, ln1_b, vnh);
    // 9) h1 = relu(vn @ w11 + b11)   [128x256, 128 blocks]
    gemm_big_relu<<<dim3(HIDD/256, MR/128), 256, GSMEMBIG>>>(
        vnh, w11h, b11, h1h, MR, HIDD, EE);
    // 10) out = v + h1 @ w12 + b12   [64x128, 128 blocks]
    gemm64_res<<<dim3(EE/128, MR/64), 256, GSMEM64>>>(
        h1h, w12h, b12, p_v, out, MR, EE, HIDD);
}

// round 17
// speedup vs baseline: 1.5055x; 1.5055x over previous
#include <cuda_runtime.h>
#include <cuda_fp16.h>
#include <cstdint>
#include <cstddef>

#define BB 4
#define SS 512
#define EE 512
#define HIDD 2048
#define HH 8
#define DD 64
#define RFULL 201
#define RUSE 101
#define MR (BB*SS)   // 2048

// ---------------- fp32 scratch ----------------------------------------------
__device__ __align__(128) float g_q [MR*EE];
__device__ __align__(128) float g_ke[MR*EE];
__device__ __align__(128) float g_krt[RFULL*EE];
__device__ __align__(128) float g_t1[RFULL*HH];
__device__ __align__(128) float g_b0t[MR*HH];
__device__ __align__(128) float g_P[(size_t)MR*HH*RUSE];
__device__ __align__(128) float g_v [MR*EE];

// ---------------- fp16 scratch ----------------------------------------------
__device__ __align__(128) __half g_xnh[MR*EE];
__device__ __align__(128) __half g_xh [MR*HIDD];
__device__ __align__(128) __half g_vnh[MR*EE];
__device__ __align__(128) __half g_h1h[MR*HIDD];
__device__ __align__(128) __half g_reh[RFULL*EE + 64], g_rel_[RFULL*EE + 64];
__device__ __align__(128) __half g_qh [MR*EE], g_ql [MR*EE];
__device__ __align__(128) __half g_keh[MR*EE];
__device__ __align__(128) __half g_kvh[MR*EE];
__device__ __align__(128) __half g_krt16[HH*128*DD];   // zero-padded rows 101..127
// weights, transposed to [N][K], single fp16
__device__ __align__(128) __half g_wb0h[HIDD*EE];
__device__ __align__(128) __half g_wqkvh[3*EE*HIDD];
__device__ __align__(128) __half g_wkrh[EE*EE];
__device__ __align__(128) __half g_w11h[HIDD*EE];
__device__ __align__(128) __half g_w12h[EE*HIDD];

// ---------------- PTX helpers -----------------------------------------------
__device__ __forceinline__ uint32_t s2u(const void* p){
    uint32_t a;
    asm("{ .reg .u64 t; cvta.to.shared.u64 t, %1; cvt.u32.u64 %0, t; }" : "=r"(a) : "l"(p));
    return a;
}
__device__ __forceinline__ void cpa16(uint32_t dst, const void* src, uint32_t sz){
    asm volatile("cp.async.cg.shared.global [%0], [%1], 16, %2;" :: "r"(dst), "l"(src), "r"(sz));
}
__device__ __forceinline__ void cpcommit(){ asm volatile("cp.async.commit_group;" ::: "memory"); }
__device__ __forceinline__ void cpwait0(){ asm volatile("cp.async.wait_group 0;" ::: "memory"); }
__device__ __forceinline__ void cpwait1(){ asm volatile("cp.async.wait_group 1;" ::: "memory"); }

__device__ __forceinline__ void ldsm4(uint32_t* r, uint32_t addr){
    asm volatile("ldmatrix.sync.aligned.m8n8.x4.shared.b16 {%0,%1,%2,%3}, [%4];"
        : "=r"(r[0]), "=r"(r[1]), "=r"(r[2]), "=r"(r[3]) : "r"(addr));
}
__device__ __forceinline__ void ldsm4t(uint32_t* r, uint32_t addr){
    asm volatile("ldmatrix.sync.aligned.m8n8.x4.trans.shared.b16 {%0,%1,%2,%3}, [%4];"
        : "=r"(r[0]), "=r"(r[1]), "=r"(r[2]), "=r"(r[3]) : "r"(addr));
}
__device__ __forceinline__ void mma16816(float* d, const uint32_t* a, const uint32_t* b){
    asm volatile("mma.sync.aligned.m16n8k16.row.col.f32.f16.f16.f32 "
        "{%0,%1,%2,%3}, {%4,%5,%6,%7}, {%8,%9}, {%0,%1,%2,%3};"
        : "+f"(d[0]), "+f"(d[1]), "+f"(d[2]), "+f"(d[3])
        : "r"(a[0]), "r"(a[1]), "r"(a[2]), "r"(a[3]), "r"(b[0]), "r"(b[1]));
}
__device__ __forceinline__ uint32_t packh(__half a, __half b){
    return (uint32_t)__half_as_ushort(a) | ((uint32_t)__half_as_ushort(b) << 16);
}

// geometry: k-chunk 64, rows padded to 72 halves (144 B)
#define KC 64
#define KSTRIDE 72
#define ROWB 144
#define TILE_B (128*ROWB)                 // 18432
#define STAGE1P (2*TILE_B)                // (A, B) 128x128 1-pass
#define GSMEM1P (2*STAGE1P)               // 73728  -> 2 CTAs/SM
#define STAGE2P (3*TILE_B)                // (Ah, Al, B)  kr only
#define GSMEM2P (2*STAGE2P)               // 110592

#define TILE_A64 (64*ROWB)                // 9216
#define STAGE64 (TILE_A64 + TILE_B)       // 27648
#define GSMEM64 (2*STAGE64)               // 55296

// flash attention: q tile 128x64, kv tiles 64x64
#define QTILE_B (128*ROWB)
#define ATILE_B (64*ROWB)
#define FA_SMEM (2*QTILE_B + 4*ATILE_B)   // 73728

// pgemm: qh tile + ql tile + krt16 tile
#define PK_SMEM (3*TILE_B)                // 55296

// ---------------- loaders ----------------------------------------------------
template<int TILES>
__device__ __forceinline__ void load_chunk128(uint32_t stage, int tid,
    const __half* __restrict__ A0, const __half* __restrict__ A1,
    const __half* __restrict__ Bh,
    int m0, int n0, int k0, int M, int K)
{
    #pragma unroll
    for (int t = 0; t < TILES; t++){
        const __half* gp = (t==0)?A0:(t==TILES-1)?Bh:A1;
        int row0 = (t < TILES-1) ? m0 : n0;
        uint32_t tb = stage + t*TILE_B;
        #pragma unroll
        for (int i = 0; i < 4; i++){
            int s = i*256 + tid;
            int r = s >> 3, seg = s & 7;
            int gr = row0 + r;
            uint32_t sz = 16u;
            if (t < TILES-1 && gr >= M){ sz = 0u; gr = M - 1; }
            cpa16(tb + (uint32_t)(r*ROWB + seg*16),
                  gp + (size_t)gr*K + k0 + seg*8, sz);
        }
    }
    cpcommit();
}

__device__ __forceinline__ void load_chunk64(uint32_t stage, int tid,
    const __half* __restrict__ A, const __half* __restrict__ B,
    int m0, int n0, int k0, int K)
{
    #pragma unroll
    for (int i = 0; i < 2; i++){
        int s = i*256 + tid;
        int r = s >> 3, seg = s & 7;
        cpa16(stage + (uint32_t)(r*ROWB + seg*16),
              A + (size_t)(m0 + r)*K + k0 + seg*8, 16u);
    }
    uint32_t tb = stage + TILE_A64;
    #pragma unroll
    for (int i = 0; i < 4; i++){
        int s = i*256 + tid;
        int r = s >> 3, seg = s & 7;
        cpa16(tb + (uint32_t)(r*ROWB + seg*16),
              B + (size_t)(n0 + r)*K + k0 + seg*8, 16u);
    }
    cpcommit();
}

// ---------------- 128x128 mainloop (PASSES = 1 or 2) -------------------------
template<int PASSES>
__device__ __forceinline__ void mainloop128(uint32_t sb, int tid, int lane, int warp,
    const __half* A0, const __half* A1, const __half* Bh,
    int m0, int n0, int M, int K, float acc[4][4][4])
{
    const int TILES = PASSES + 1;
    const int STG = TILES*TILE_B;
    int a_row  = (warp >> 2)*64 + (lane & 15);
    int a_col8 = (lane >> 4)*8;
    int b_row  = (warp & 3)*32 + (lane & 7) + ((lane & 16) ? 8 : 0);
    int b_col8 = ((lane & 8) ? 8 : 0);

    const int NC = K / KC;
    uint32_t st0 = sb, st1 = sb + STG;
    load_chunk128<TILES>(st0, tid, A0, A1, Bh, m0, n0, 0, M, K);

    for (int c = 0; c < NC; c++){
        uint32_t cur = (c & 1) ? st1 : st0;
        if (c + 1 < NC)
            load_chunk128<TILES>((c & 1) ? st0 : st1, tid, A0, A1, Bh, m0, n0, (c+1)*KC, M, K);
        if (c + 1 < NC) cpwait1(); else cpwait0();
        __syncthreads();

        uint32_t cA0 = cur, cA1 = cur + TILE_B, cB = cur + (TILES-1)*TILE_B;
        #pragma unroll
        for (int ks = 0; ks < 4; ks++){
            int k0 = ks*16;
            uint32_t a0[4][4], a1[4][4], bh[2][4];
            #pragma unroll
            for (int mt = 0; mt < 4; mt++){
                uint32_t off = (uint32_t)((a_row + mt*16)*KSTRIDE + k0 + a_col8)*2u;
                ldsm4(a0[mt], cA0 + off);
                if (PASSES == 2) ldsm4(a1[mt], cA1 + off);
            }
            #pragma unroll
            for (int p = 0; p < 2; p++){
                uint32_t off = (uint32_t)((b_row + p*16)*KSTRIDE + k0 + b_col8)*2u;
                ldsm4(bh[p], cB + off);
            }
            #pragma unroll
            for (int mt = 0; mt < 4; mt++)
                #pragma unroll
                for (int nt = 0; nt < 4; nt++)
                    mma16816(acc[mt][nt], a0[mt], &bh[nt >> 1][(nt & 1)*2]);
            if (PASSES == 2){
                #pragma unroll
                for (int mt = 0; mt < 4; mt++)
                    #pragma unroll
                    for (int nt = 0; nt < 4; nt++)
                        mma16816(acc[mt][nt], a1[mt], &bh[nt >> 1][(nt & 1)*2]);
            }
        }
        __syncthreads();
    }
}

// EPI: 0 fp32+bias, 1 relu->fp16, 2 fp32+bias+res ; PASSES 1 or 2
template<int EPI, int PASSES>
__global__ __launch_bounds__(256, 2)
void gemm128(const __half* A0, const __half* A1, const __half* Bh,
             const float* __restrict__ bias, const float* __restrict__ res,
             float* __restrict__ Cf, __half* __restrict__ Ch,
             int M, int N, int K)
{
    extern __shared__ char smem[];
    uint32_t sb = s2u(smem);
    int tid = threadIdx.x, lane = tid & 31, warp = tid >> 5;
    int m0 = blockIdx.y*128, n0 = blockIdx.x*128;
    float acc[4][4][4];
    #pragma unroll
    for (int a = 0; a < 4; a++)
        #pragma unroll
        for (int b = 0; b < 4; b++)
            #pragma unroll
            for (int c = 0; c < 4; c++) acc[a][b][c] = 0.f;

    mainloop128<PASSES>(sb, tid, lane, warp, A0, A1, Bh, m0, n0, M, K, acc);

    int gg = lane >> 2, tig = lane & 3;
    int wm = warp >> 2, wn = warp & 3;
    #pragma unroll
    for (int mt = 0; mt < 4; mt++)
        #pragma unroll
        for (int half = 0; half < 2; half++){
            int row = m0 + wm*64 + mt*16 + gg + half*8;
            if (row >= M) continue;
            #pragma unroll
            for (int nt = 0; nt < 4; nt++){
                int col = n0 + wn*32 + nt*8 + tig*2;
                float v0 = acc[mt][nt][half*2 + 0] + bias[col];
                float v1 = acc[mt][nt][half*2 + 1] + bias[col + 1];
                size_t o = (size_t)row*N + col;
                if (EPI == 1){
                    v0 = fmaxf(v0, 0.f); v1 = fmaxf(v1, 0.f);
                    *(uint32_t*)((char*)Ch + o*2) = packh(__float2half_rn(v0), __float2half_rn(v1));
                } else {
                    if (EPI == 2){
                        float2 rv = *(const float2*)&res[o];
                        v0 += rv.x; v1 += rv.y;
                    }
                    *(float2*)&Cf[o] = make_float2(v0, v1);
                }
            }
        }
}

// merged qkv on 128x128 tiles: N=1536, z = blockIdx.x>>2
__global__ __launch_bounds__(256, 2)
void gemm_qkv128(const __half* Ah, const __half* Bh,
                 const float* b0, const float* b1, const float* b2,
                 float* f0, float* f1,
                 __half* c0h, __half* c0l, __half* c1h, __half* c2h,
                 int M, int K)
{
    extern __shared__ char smem[];
    uint32_t sb = s2u(smem);
    int tid = threadIdx.x, lane = tid & 31, warp = tid >> 5;
    int m0 = blockIdx.y*128, n0 = blockIdx.x*128;
    float acc[4][4][4];
    #pragma unroll
    for (int a = 0; a < 4; a++)
        #pragma unroll
        for (int b = 0; b < 4; b++)
            #pragma unroll
            for (int c = 0; c < 4; c++) acc[a][b][c] = 0.f;

    mainloop128<1>(sb, tid, lane, warp, Ah, nullptr, Bh, m0, n0, M, K, acc);

    int z = blockIdx.x >> 2;
    const float* bias = (z==0)?b0:(z==1)?b1:b2;
    float* Cf = (z==0)?f0:(z==1)?f1:nullptr;
    __half* Ch = (z==0)?c0h:(z==1)?c1h:c2h;
    __half* Cl = (z==0)?c0l:nullptr;
    int n0l = (blockIdx.x & 3)*128;

    int gg = lane >> 2, tig = lane & 3;
    int wm = warp >> 2, wn = warp & 3;
    #pragma unroll
    for (int mt = 0; mt < 4; mt++)
        #pragma unroll
        for (int half = 0; half < 2; half++){
            int row = m0 + wm*64 + mt*16 + gg + half*8;
            #pragma unroll
            for (int nt = 0; nt < 4; nt++){
                int col = n0l + wn*32 + nt*8 + tig*2;
                float v0 = acc[mt][nt][half*2 + 0] + bias[col];
                float v1 = acc[mt][nt][half*2 + 1] + bias[col + 1];
                size_t o = (size_t)row*512 + col;
                if (Cf) *(float2*)&Cf[o] = make_float2(v0, v1);
                __half h0 = __float2half_rn(v0);
                __half h1 = __float2half_rn(v1);
                *(uint32_t*)((char*)Ch + o*2) = packh(h0, h1);
                if (Cl){
                    __half l0 = __float2half_rn(v0 - __half2float(h0));
                    __half l1 = __float2half_rn(v1 - __half2float(h1));
                    *(uint32_t*)((char*)Cl + o*2) = packh(l0, l1);
                }
            }
        }
}

// ---------------- 64x128 GEMM (FFN2) -----------------------------------------
__global__ __launch_bounds__(256, 2)
void gemm64_res(const __half* __restrict__ A, const __half* __restrict__ B,
                const float* __restrict__ bias, const float* __restrict__ res,
                float* __restrict__ Cf, int M, int N, int K)
{
    extern __shared__ char smem[];
    uint32_t sb = s2u(smem);
    int tid = threadIdx.x, lane = tid & 31, warp = tid >> 5;
    int m0 = blockIdx.y*64, n0 = blockIdx.x*128;

    int a_row  = (warp >> 2)*32 + (lane & 15);
    int a_col8 = (lane >> 4)*8;
    int b_row  = (warp & 3)*32 + (lane & 7) + ((lane & 16) ? 8 : 0);
    int b_col8 = ((lane & 8) ? 8 : 0);

    float acc[2][4][4];
    #pragma unroll
    for (int a = 0; a < 2; a++)
        #pragma unroll
        for (int b = 0; b < 4; b++)
            #pragma unroll
            for (int c = 0; c < 4; c++) acc[a][b][c] = 0.f;

    const int NC = K / KC;
    uint32_t st0 = sb, st1 = sb + STAGE64;
    load_chunk64(st0, tid, A, B, m0, n0, 0, K);

    for (int c = 0; c < NC; c++){
        uint32_t cur = (c & 1) ? st1 : st0;
        if (c + 1 < NC)
            load_chunk64((c & 1) ? st0 : st1, tid, A, B, m0, n0, (c+1)*KC, K);
        if (c + 1 < NC) cpwait1(); else cpwait0();
        __syncthreads();

        uint32_t cA = cur, cB = cur + TILE_A64;
        #pragma unroll
        for (int ks = 0; ks < 4; ks++){
            int k0 = ks*16;
            uint32_t af[2][4], bh[2][4];
            #pragma unroll
            for (int mt = 0; mt < 2; mt++){
                uint32_t off = (uint32_t)((a_row + mt*16)*KSTRIDE + k0 + a_col8)*2u;
                ldsm4(af[mt], cA + off);
            }
            #pragma unroll
            for (int p = 0; p < 2; p++){
                uint32_t off = (uint32_t)((b_row + p*16)*KSTRIDE + k0 + b_col8)*2u;
                ldsm4(bh[p], cB + off);
            }
            #pragma unroll
            for (int mt = 0; mt < 2; mt++)
                #pragma unroll
                for (int nt = 0; nt < 4; nt++)
                    mma16816(acc[mt][nt], af[mt], &bh[nt >> 1][(nt & 1)*2]);
        }
        __syncthreads();
    }

    int gg = lane >> 2, tig = lane & 3;
    int wm = warp >> 2, wn = warp & 3;
    #pragma unroll
    for (int mt = 0; mt < 2; mt++)
        #pragma unroll
        for (int half = 0; half < 2; half++){
            int row = m0 + wm*32 + mt*16 + gg + half*8;
            #pragma unroll
            for (int nt = 0; nt < 4; nt++){
                int col = n0 + wn*32 + nt*8 + tig*2;
                float v0 = acc[mt][nt][half*2 + 0] + bias[col];
                float v1 = acc[mt][nt][half*2 + 1] + bias[col + 1];
                size_t o = (size_t)row*N + col;
                float2 rv = *(const float2*)&res[o];
                *(float2*)&Cf[o] = make_float2(v0 + rv.x, v1 + rv.y);
            }
        }
}

// ---------------- krt fp32 -> fp16 (zero-padded to 128 rows) -----------------
__global__ void convK(const float* __restrict__ krt, __half* __restrict__ K16)
{
    int idx = blockIdx.x*256 + threadIdx.x;      // over 8*128*64 = 65536
    int h = idx >> 13;
    int rk = idx & 8191;
    int row = rk >> 6, k = rk & 63;
    float v = (row < RUSE) ? krt[(size_t)row*EE + h*DD + k] : 0.f;
    K16[idx] = __float2half_rn(v);
}

// ---------------- tensor-core P table: P[m,h,r] = q_h(m).krt_h(r) + t1[r,h] --
// grid (16 m-tiles, 8 h), block 256 (8 warps x 16 rows)
__global__ __launch_bounds__(256, 1)
void pgemm(const __half* __restrict__ qh, const __half* __restrict__ ql,
           const __half* __restrict__ K16,
           const float* __restrict__ t1, float* __restrict__ P)
{
    extern __shared__ char smem[];
    uint32_t sb = s2u(smem);
    int tid = threadIdx.x, lane = tid & 31, warp = tid >> 5;
    int m0 = blockIdx.x*128, h = blockIdx.y;

    uint32_t sAh = sb, sAl = sb + TILE_B, sB = sb + 2*TILE_B;
    #pragma unroll
    for (int t = 0; t < 2; t++){
        const __half* gp = t ? ql : qh;
        uint32_t tb = t ? sAl : sAh;
        #pragma unroll
        for (int i = 0; i < 4; i++){
            int s = i*256 + tid;
            int r = s >> 3, seg = s & 7;
            cpa16(tb + (uint32_t)(r*ROWB + seg*16),
                  gp + (size_t)(m0 + r)*EE + h*DD + seg*8, 16u);
        }
    }
    #pragma unroll
    for (int i = 0; i < 4; i++){
        int s = i*256 + tid;
        int r = s >> 3, seg = s & 7;
        cpa16(sB + (uint32_t)(r*ROWB + seg*16),
              K16 + (size_t)h*128*DD + r*DD + seg*8, 16u);
    }
    cpcommit(); cpwait0();
    __syncthreads();

    int a_row  = warp*16 + (lane & 15);
    int a_col8 = (lane >> 4)*8;
    int b_row  = (lane & 7) + ((lane & 16) ? 8 : 0);
    int b_col8 = ((lane & 8) ? 8 : 0);

    float acc[16][4];
    #pragma unroll
    for (int nt = 0; nt < 16; nt++)
        #pragma unroll
        for (int c = 0; c < 4; c++) acc[nt][c] = 0.f;

    #pragma unroll
    for (int ks = 0; ks < 4; ks++){
        int k0 = ks*16;
        uint32_t aq[4], aql[4], bf[8][4];
        uint32_t offA = (uint32_t)(a_row*KSTRIDE + k0 + a_col8)*2u;
        ldsm4(aq,  sAh + offA);
        ldsm4(aql, sAl + offA);
        #pragma unroll
        for (int p = 0; p < 8; p++){
            uint32_t off = (uint32_t)((p*16 + b_row)*KSTRIDE + k0 + b_col8)*2u;
            ldsm4(bf[p], sB + off);
        }
        #pragma unroll
        for (int nt = 0; nt < 16; nt++)
            mma16816(acc[nt], aq, &bf[nt >> 1][(nt & 1)*2]);
        #pragma unroll
        for (int nt = 0; nt < 16; nt++)
            mma16816(acc[nt], aql, &bf[nt >> 1][(nt & 1)*2]);
    }

    int gg = lane >> 2, tig = lane & 3;
    #pragma unroll
    for (int half = 0; half < 2; half++){
        int m = m0 + warp*16 + gg + half*8;
        float* Pp = P + ((size_t)m*HH + h)*RUSE;
        #pragma unroll
        for (int nt = 0; nt < 16; nt++){
            #pragma unroll
            for (int e = 0; e < 2; e++){
                int r = nt*8 + tig*2 + e;
                if (r < RUSE)
                    Pp[r] = acc[nt][half*2 + e] + t1[r*HH + h];
            }
        }
    }
}

// ---------------- fused flash attention: 128-row q tiles ---------------------
__global__ __launch_bounds__(256) void flash_att(
    const __half* __restrict__ qh, const __half* __restrict__ ql,
    const __half* __restrict__ keh, const __half* __restrict__ kvh,
    const float* __restrict__ P, const float* __restrict__ b0t,
    const float* __restrict__ vals, float* __restrict__ V)
{
    extern __shared__ char smem[];
    uint32_t sb = s2u(smem);
    int tid = threadIdx.x, lane = tid & 31, warp = tid >> 5;
    int it = blockIdx.x, bh = blockIdx.y, b = bh >> 3, h = bh & 7;
    int i0 = it*128;
    int NCH = 2*it + 2;

    uint32_t sQH = sb, sQL = sb + QTILE_B;
    uint32_t st0 = sb + 2*QTILE_B;
    uint32_t st1 = st0 + 2*ATILE_B;

    #pragma unroll
    for (int t = 0; t < 2; t++){
        const __half* gp = t ? ql : qh;
        uint32_t tb = t ? sQL : sQH;
        #pragma unroll
        for (int i = 0; i < 4; i++){
            int s = i*256 + tid;
            int r = s >> 3, seg = s & 7;
            cpa16(tb + (uint32_t)(r*ROWB + seg*16),
                  gp + ((size_t)(b*SS + i0 + r))*EE + h*DD + seg*8, 16u);
        }
    }
    #pragma unroll
    for (int t = 0; t < 2; t++){
        const __half* gp = t ? kvh : keh;
        uint32_t tb = st0 + t*ATILE_B;
        #pragma unroll
        for (int i = 0; i < 2; i++){
            int s = i*256 + tid;
            int r = s >> 3, seg = s & 7;
            cpa16(tb + (uint32_t)(r*ROWB + seg*16),
                  gp + ((size_t)(b*SS + r))*EE + h*DD + seg*8, 16u);
        }
    }
    cpcommit();

    int gg = lane >> 2, tig = lane & 3;
    int a_row  = warp*16 + (lane & 15);
    int a_col8 = (lane >> 4)*8;
    int b_rowb = (lane & 7) + ((lane & 16) ? 8 : 0);
    int b_col8 = ((lane & 8) ? 8 : 0);
    int bt_row = lane & 15;
    int bt_colb = ((lane & 16) ? 8 : 0);

    int gi0 = i0 + warp*16 + gg;
    int gi1 = gi0 + 8;
    const float* Pr0 = P + ((size_t)(b*SS + gi0)*HH + h)*RUSE + 100;
    const float* Pr1 = P + ((size_t)(b*SS + gi1)*HH + h)*RUSE + 100;

    float m_st[2] = {-1e30f, -1e30f};
    float l_st[2] = {0.f, 0.f};
    float acc_o[8][4];
    #pragma unroll
    for (int nt = 0; nt < 8; nt++)
        #pragma unroll
        for (int c = 0; c < 4; c++) acc_o[nt][c] = 0.f;

    for (int c = 0; c < NCH; c++){
        uint32_t cur = (c & 1) ? st1 : st0;
        if (c + 1 < NCH){
            uint32_t nxt = (c & 1) ? st0 : st1;
            int j0n = (c + 1)*64;
            #pragma unroll
            for (int t = 0; t < 2; t++){
                const __half* gp = t ? kvh : keh;
                uint32_t tb = nxt + t*ATILE_B;
                #pragma unroll
                for (int i = 0; i < 2; i++){
                    int s = i*256 + tid;
                    int r = s >> 3, seg = s & 7;
                    cpa16(tb + (uint32_t)(r*ROWB + seg*16),
                          gp + ((size_t)(b*SS + j0n + r))*EE + h*DD + seg*8, 16u);
                }
            }
            cpcommit();
        }
        if (c + 1 < NCH) cpwait1(); else cpwait0();
        __syncthreads();

        int j0 = c*64;
        uint32_t cK = cur, cV = cur + ATILE_B;

        float s_acc[8][4];
        #pragma unroll
        for (int nt = 0; nt < 8; nt++)
            #pragma unroll
            for (int e = 0; e < 4; e++) s_acc[nt][e] = 0.f;
        #pragma unroll
        for (int ks = 0; ks < 4; ks++){
            int k0 = ks*16;
            uint32_t aq[4], aql[4], bf[4][4];
            uint32_t offA = (uint32_t)(a_row*KSTRIDE + k0 + a_col8)*2u;
            ldsm4(aq,  sQH + offA);
            ldsm4(aql, sQL + offA);
            #pragma unroll
            for (int p = 0; p < 4; p++){
                uint32_t off = (uint32_t)((p*16 + b_rowb)*KSTRIDE + k0 + b_col8)*2u;
                ldsm4(bf[p], cK + off);
            }
            #pragma unroll
            for (int nt = 0; nt < 8; nt++)
                mma16816(s_acc[nt], aq, &bf[nt >> 1][(nt & 1)*2]);
            #pragma unroll
            for (int nt = 0; nt < 8; nt++)
                mma16816(s_acc[nt], aql, &bf[nt >> 1][(nt & 1)*2]);
        }

        float rowmax[2] = {-1e30f, -1e30f};
        #pragma unroll
        for (int nt = 0; nt < 8; nt++){
            #pragma unroll
            for (int e = 0; e < 2; e++){
                int j = j0 + nt*8 + tig*2 + e;
                float bv = b0t[(size_t)(b*SS + j)*HH + h];
                #pragma unroll
                for (int hh = 0; hh < 2; hh++){
                    int gi = hh ? gi1 : gi0;
                    int ci = hh*2 + e;
                    float val;
                    if (j > gi){
                        val = -1e30f;
                    } else {
                        int off = j - gi;
                        if (off < -100) off = -100;
                        val = s_acc[nt][ci]*0.125f + (hh ? Pr1 : Pr0)[off] + bv;
                    }
                    s_acc[nt][ci] = val;
                    rowmax[hh] = fmaxf(rowmax[hh], val);
                }
            }
        }
        #pragma unroll
        for (int hh = 0; hh < 2; hh++){
            rowmax[hh] = fmaxf(rowmax[hh], __shfl_xor_sync(0xffffffffu, rowmax[hh], 1));
            rowmax[hh] = fmaxf(rowmax[hh], __shfl_xor_sync(0xffffffffu, rowmax[hh], 2));
        }
        float mnew[2], scale[2], rsum[2] = {0.f, 0.f};
        #pragma unroll
        for (int hh = 0; hh < 2; hh++){
            mnew[hh]  = fmaxf(m_st[hh], rowmax[hh]);
            scale[hh] = __expf(m_st[hh] - mnew[hh]);
            m_st[hh]  = mnew[hh];
        }
        #pragma unroll
        for (int nt = 0; nt < 8; nt++)
            #pragma unroll
            for (int ci = 0; ci < 4; ci++){
                int hh = ci >> 1;
                float p = __expf(s_acc[nt][ci] - mnew[hh]);
                s_acc[nt][ci] = p;
                rsum[hh] += p;
            }
        #pragma unroll
        for (int hh = 0; hh < 2; hh++){
            rsum[hh] += __shfl_xor_sync(0xffffffffu, rsum[hh], 1);
            rsum[hh] += __shfl_xor_sync(0xffffffffu, rsum[hh], 2);
            l_st[hh] = l_st[hh]*scale[hh] + rsum[hh];
        }
        #pragma unroll
        for (int nt = 0; nt < 8; nt++)
            #pragma unroll
            for (int ci = 0; ci < 4; ci++)
                acc_o[nt][ci] *= scale[ci >> 1];

        uint32_t pa[4][4], pl[4][4];
        #pragma unroll
        for (int ks2 = 0; ks2 < 4; ks2++){
            #pragma unroll
            for (int half8 = 0; half8 < 2; half8++){
                int nt = ks2*2 + half8;
                __half h0 = __float2half_rn(s_acc[nt][0]);
                __half h1 = __float2half_rn(s_acc[nt][1]);
                __half h2 = __float2half_rn(s_acc[nt][2]);
                __half h3 = __float2half_rn(s_acc[nt][3]);
                pa[ks2][0 + half8*2] = packh(h0, h1);
                pa[ks2][1 + half8*2] = packh(h2, h3);
                __half l0 = __float2half_rn(s_acc[nt][0] - __half2float(h0));
                __half l1 = __float2half_rn(s_acc[nt][1] - __half2float(h1));
                __half l2 = __float2half_rn(s_acc[nt][2] - __half2float(h2));
                __half l3 = __float2half_rn(s_acc[nt][3] - __half2float(h3));
                pl[ks2][0 + half8*2] = packh(l0, l1);
                pl[ks2][1 + half8*2] = packh(l2, l3);
            }
        }

        #pragma unroll
        for (int ks2 = 0; ks2 < 4; ks2++){
            int k0 = ks2*16;
            uint32_t bv[4][4];
            #pragma unroll
            for (int grp = 0; grp < 4; grp++){
                uint32_t off = (uint32_t)((k0 + bt_row)*KSTRIDE + grp*16 + bt_colb)*2u;
                ldsm4t(bv[grp], cV + off);
            }
            #pragma unroll
            for (int nt = 0; nt < 8; nt++)
                mma16816(acc_o[nt], pa[ks2], &bv[nt >> 1][(nt & 1)*2]);
            #pragma unroll
            for (int nt = 0; nt < 8; nt++)
                mma16816(acc_o[nt], pl[ks2], &bv[nt >> 1][(nt & 1)*2]);
        }
        __syncthreads();
    }

    float inv[2] = {1.f / l_st[0], 1.f / l_st[1]};
    #pragma unroll
    for (int hh = 0; hh < 2; hh++){
        int gi = hh ? gi1 : gi0;
        #pragma unroll
        for (int nt = 0; nt < 8; nt++){
            int d = nt*8 + tig*2;
            size_t o = ((size_t)(b*SS + gi))*EE + h*DD + d;
            float2 rv = *(const float2*)&vals[o];
            *(float2*)&V[o] = make_float2(acc_o[nt][hh*2 + 0]*inv[hh] + rv.x,
                                          acc_o[nt][hh*2 + 1]*inv[hh] + rv.y);
        }
    }
}

// ---------------- fused weight conversion ------------------------------------
struct WTab {
    const float* W[7];
    __half* Th[7];
    int K[7];
    int N[7];
    int off[8];
};

__global__ void convWT_all(WTab tab)
{
    __shared__ float t[32][33];
    int bid = blockIdx.x;
    int e = 0;
    #pragma unroll
    for (int i = 1; i < 7; i++) if (bid >= tab.off[i]) e = i;
    int local = bid - tab.off[e];
    const float* W = tab.W[e];
    __half* Th = tab.Th[e];
    int K = tab.K[e], N = tab.N[e];
    int ntiles = N >> 5;
    int kt = local / ntiles, ct = local - kt*ntiles;
    int by = kt*32, bx = ct*32;
    int lx = threadIdx.x & 31, ly = threadIdx.x >> 5;
    #pragma unroll
    for (int i = 0; i < 32; i += 8)
        t[ly + i][lx] = W[(size_t)(by + ly + i)*N + bx + lx];
    __syncthreads();
    #pragma unroll
    for (int i = 0; i < 32; i += 8){
        int n = bx + ly + i, k = by + lx;
        Th[(size_t)n*K + k] = __float2half_rn(t[lx][ly + i]);
    }
}

__global__ void convA(const float* __restrict__ X, __half* __restrict__ H,
                      __half* __restrict__ L, int n)
{
    int i = blockIdx.x*256 + threadIdx.x;
    if (i < n){
        float x = X[i];
        __half h = __float2half_rn(x);
        H[i] = h;
        L[i] = __float2half_rn(x - __half2float(h));
    }
}

// ---------------- LayerNorm -> fp16 hi only ---------------------------------
__global__ void ln_h(const float* __restrict__ X, const float* __restrict__ g,
                     const float* __restrict__ bt, __half* __restrict__ Yh)
{
    int row = blockIdx.x;
    int tid = threadIdx.x;
    const float* x = X + (size_t)row*EE;
    float a = x[tid], c = x[tid + 256];
    float s  = a + c;
    float s2 = a*a + c*c;
    #pragma unroll
    for (int o = 16; o > 0; o >>= 1){
        s  += __shfl_xor_sync(0xffffffffu, s,  o);
        s2 += __shfl_xor_sync(0xffffffffu, s2, o);
    }
    __shared__ float sa[8], sbm[8];
    if ((tid & 31) == 0){ sa[tid>>5] = s; sbm[tid>>5] = s2; }
    __syncthreads();
    float ts = 0.f, ts2 = 0.f;
    #pragma unroll
    for (int w = 0; w < 8; w++){ ts += sa[w]; ts2 += sbm[w]; }
    float mean = ts * (1.f/512.f);
    float var  = ts2 * (1.f/512.f) - mean*mean;
    float r = rsqrtf(var + 1e-3f);
    Yh[(size_t)row*EE + tid]       = __float2half_rn((a - mean)*r*g[tid]       + bt[tid]);
    Yh[(size_t)row*EE + tid + 256] = __float2half_rn((c - mean)*r*g[tid + 256] + bt[tid + 256]);
}

// ---------------- fused dual N=8 projection ----------------------------------
__global__ void proj8_dual(
    const float* __restrict__ X0, const float* __restrict__ W0,
    const float* __restrict__ bp0, float* __restrict__ Y0, int n0,
    const float* __restrict__ X1, const float* __restrict__ W1,
    const float* __restrict__ bp1, float* __restrict__ Y1)
{
    int row = blockIdx.x;
    const float *X, *Wp, *bp;
    float* Y;
    int r;
    if (row < n0){ X = X0; Wp = W0; bp = bp0; Y = Y0; r = row; }
    else         { X = X1; Wp = W1; bp = bp1; Y = Y1; r = row - n0; }
    int tid = threadIdx.x;
    int h = tid & 7, seg = tid >> 3;
    const float* x = X + (size_t)r*EE;
    float s = 0.f;
    #pragma unroll
    for (int k = 0; k < 16; k++){
        int kk = seg*16 + k;
        s += x[kk] * Wp[kk*HH + h];
    }
    __shared__ float sm[256];
    sm[tid] = s;
    __syncthreads();
    if (tid < 8){
        float acc = bp[tid];
        #pragma unroll
        for (int sg = 0; sg < 32; sg++) acc += sm[sg*8 + tid];
        Y[(size_t)r*HH + tid] = acc;
    }
}

// ---------------- launch ----------------------------------------------------
extern "C" void kernel_launch(void* const* d_in, const int* in_sizes, int n_in,
                              void* d_out, int out_size)
{
    const float* values  = (const float*)d_in[0];
    const float* rel_enc = (const float*)d_in[2];
    const float* ln0_g   = (const float*)d_in[3];
    const float* ln0_b   = (const float*)d_in[4];
    const float* w_b0    = (const float*)d_in[5];
    const float* b_b0    = (const float*)d_in[6];
    const float* wq      = (const float*)d_in[7];
    const float* bq      = (const float*)d_in[8];
    const float* wke     = (const float*)d_in[9];
    const float* bke     = (const float*)d_in[10];
    const float* wkv     = (const float*)d_in[11];
    const float* bkv     = (const float*)d_in[12];
    const float* wkr     = (const float*)d_in[13];
    const float* bkr     = (const float*)d_in[14];
    const float* wab0    = (const float*)d_in[15];
    const float* bab0    = (const float*)d_in[16];
    const float* wab1    = (const float*)d_in[17];
    const float* bab1    = (const float*)d_in[18];
    const float* ln1_g   = (const float*)d_in[19];
    const float* ln1_b   = (const float*)d_in[20];
    const float* w11     = (const float*)d_in[21];
    const float* b11     = (const float*)d_in[22];
    const float* w12     = (const float*)d_in[23];
    const float* b12     = (const float*)d_in[24];
    float* out = (float*)d_out;

    float *p_q,*p_ke,*p_krt,*p_t1,*p_b0t,*p_P,*p_v;
    cudaGetSymbolAddress((void**)&p_q,   g_q);
    cudaGetSymbolAddress((void**)&p_ke,  g_ke);
    cudaGetSymbolAddress((void**)&p_krt, g_krt);
    cudaGetSymbolAddress((void**)&p_t1,  g_t1);
    cudaGetSymbolAddress((void**)&p_b0t, g_b0t);
    cudaGetSymbolAddress((void**)&p_P,   g_P);
    cudaGetSymbolAddress((void**)&p_v,   g_v);

    __half *xnh,*xh,*vnh,*h1h,*reh,*rel,*krt16;
    __half *qh,*ql,*keh,*kvh;
    __half *wb0h,*wqkvh,*wkrh,*w11h,*w12h;
    cudaGetSymbolAddress((void**)&xnh, g_xnh);
    cudaGetSymbolAddress((void**)&xh,  g_xh);
    cudaGetSymbolAddress((void**)&vnh, g_vnh);
    cudaGetSymbolAddress((void**)&h1h, g_h1h);
    cudaGetSymbolAddress((void**)&reh, g_reh); cudaGetSymbolAddress((void**)&rel, g_rel_);
    cudaGetSymbolAddress((void**)&krt16, g_krt16);
    cudaGetSymbolAddress((void**)&qh,  g_qh);  cudaGetSymbolAddress((void**)&ql,  g_ql);
    cudaGetSymbolAddress((void**)&keh, g_keh);
    cudaGetSymbolAddress((void**)&kvh, g_kvh);
    cudaGetSymbolAddress((void**)&wb0h, g_wb0h);
    cudaGetSymbolAddress((void**)&wqkvh, g_wqkvh);
    cudaGetSymbolAddress((void**)&wkrh, g_wkrh);
    cudaGetSymbolAddress((void**)&w11h, g_w11h);
    cudaGetSymbolAddress((void**)&w12h, g_w12h);

    cudaFuncSetAttribute((const void*)gemm128<0,2>, cudaFuncAttributeMaxDynamicSharedMemorySize, GSMEM2P);
    cudaFuncSetAttribute((const void*)gemm128<1,1>, cudaFuncAttributeMaxDynamicSharedMemorySize, GSMEM1P);
    cudaFuncSetAttribute(gemm_qkv128, cudaFuncAttributeMaxDynamicSharedMemorySize, GSMEM1P);
    cudaFuncSetAttribute(gemm64_res,  cudaFuncAttributeMaxDynamicSharedMemorySize, GSMEM64);
    cudaFuncSetAttribute(pgemm,       cudaFuncAttributeMaxDynamicSharedMemorySize, PK_SMEM);
    cudaFuncSetAttribute(flash_att,   cudaFuncAttributeMaxDynamicSharedMemorySize, FA_SMEM);

    WTab tab;
    tab.W[0]=w_b0; tab.Th[0]=wb0h;              tab.K[0]=EE;   tab.N[0]=HIDD;
    tab.W[1]=wq;   tab.Th[1]=wqkvh;             tab.K[1]=HIDD; tab.N[1]=EE;
    tab.W[2]=wke;  tab.Th[2]=wqkvh + 512*HIDD;  tab.K[2]=HIDD; tab.N[2]=EE;
    tab.W[3]=wkv;  tab.Th[3]=wqkvh + 1024*HIDD; tab.K[3]=HIDD; tab.N[3]=EE;
    tab.W[4]=wkr;  tab.Th[4]=wkrh;              tab.K[4]=EE;   tab.N[4]=EE;
    tab.W[5]=w11;  tab.Th[5]=w11h;              tab.K[5]=EE;   tab.N[5]=HIDD;
    tab.W[6]=w12;  tab.Th[6]=w12h;              tab.K[6]=HIDD; tab.N[6]=EE;
    int total = 0;
    for (int i = 0; i < 7; i++){
        tab.off[i] = total;
        total += (tab.K[i]/32) * (tab.N[i]/32);
    }
    tab.off[7] = total;
    convWT_all<<<total, 256>>>(tab);
    convA<<<(RFULL*EE + 255)/256, 256>>>(rel_enc, reh, rel, RFULL*EE);

    // 1) LN0 -> fp16
    ln_h<<<MR, 256>>>(values, ln0_g, ln0_b, xnh);
    // 2) x = relu(xn @ w_b0 + b_b0)  [128x128, 256 blocks, occ 2]  (R15 config)
    gemm128<1,1><<<dim3(HIDD/128, MR/128), 256, GSMEM1P>>>(
        xnh, nullptr, wb0h, b_b0, nullptr, nullptr, xh, MR, HIDD, EE);
    // 3) merged q/ke/kv              [128x128, 192 blocks, occ 2]
    gemm_qkv128<<<dim3(12, MR/128), 256, GSMEM1P>>>(
        xh, wqkvh, bq, bke, bkv, p_q, p_ke, qh, ql, keh, kvh, MR, HIDD);
    // 4) kr_table (2-pass)
    gemm128<0,2><<<dim3(EE/128, 2), 256, GSMEM2P>>>(
        reh, rel, wkrh, bkr, nullptr, p_krt, nullptr, RFULL, EE, EE);
    // 5) bias0 + t1 (fused); krt -> fp16 padded
    proj8_dual<<<MR + RFULL, 256>>>(p_ke, wab0, bab0, p_b0t, MR,
                                    p_krt, wab1, bab1, p_t1);
    convK<<<(HH*128*DD)/256, 256>>>(p_krt, krt16);
    // 6) P via tensor cores          [128 blocks]  (single change vs R15)
    pgemm<<<dim3(MR/128, HH), 256, PK_SMEM>>>(qh, ql, krt16, p_t1, p_P);
    // 7) fused flash attention -> v
    flash_att<<<dim3(4, BB*HH), 256, FA_SMEM>>>(
        qh, ql, keh, kvh, p_P, p_b0t, values, p_v);
    // 8) LN1 -> fp16
    ln_h<<<MR, 256>>>(p_v, ln1_g, ln1_b, vnh);
    // 9) h1 = relu(vn @ w11 + b11)   [128x128, 256 blocks]
    gemm128<1,1><<<dim3(HIDD/128, MR/128), 256, GSMEM1P>>>(
        vnh, nullptr, w11h, b11, nullptr, nullptr, h1h, MR, HIDD, EE);
    // 10) out = v + h1 @ w12 + b12   [64x128, 128 blocks]
    gemm64_res<<<dim3(EE/128, MR/64), 256, GSMEM64>>>(
        h1h, w12h, b12, p_v, out, MR, EE, HIDD);
}